// round 6
// baseline (speedup 1.0000x reference)
#include <cuda_runtime.h>
#include <math_constants.h>

// TropicalConv2D (max-plus 3x3 depthwise), x:(8,64,224,224) f32, k:(64,1,3,3), s=1,p=1,d=1.
// R6: shared-memory strip tile (30 rows x 232 floats, -inf halos baked in).
//     Compute = pure LDS + FP, no shuffles, no predication; low regs -> full occupancy.

#define XB 8
#define XC 64
#define XH 224
#define XW 224
#define ROWS 28                  // output rows per block
#define SROWS (ROWS + 2)         // 30 input rows staged
#define SMW 232                  // smem row stride in floats (4 pad | 224 data | 4 pad)
#define SMW4 (SMW / 4)           // 58 float4 slots per row
#define STRIPS (XH / ROWS)       // 8 strips per plane

#define NEG_INF (-CUDART_INF_F)

__global__ __launch_bounds__(256) void tropical_conv3x3_smem(
    const float* __restrict__ x,
    const float* __restrict__ kern,
    float* __restrict__ out)
{
    __shared__ float4 sm4[SROWS * SMW4];       // 27840 B
    float* sm = reinterpret_cast<float*>(sm4);

    const int tid   = threadIdx.x;
    const int plane = blockIdx.x >> 3;         // b*C + c
    const int strip = blockIdx.x & 7;
    const int row0  = strip * ROWS;

    const float* pp = x + (size_t)plane * (XH * XW);

    // ---- Load stage: 30 rows x 58 float4 slots. Slot 0 / 57 are -inf halos;
    //      out-of-image rows are fully -inf. Coalesced float4 gmem reads.
    for (int s = tid; s < SROWS * SMW4; s += 256) {
        const int sr   = s / SMW4;
        const int slot = s - sr * SMW4;
        const int g    = row0 - 1 + sr;
        float4 v = make_float4(NEG_INF, NEG_INF, NEG_INF, NEG_INF);
        if ((unsigned)g < (unsigned)XH && slot >= 1 && slot <= 56)
            v = *reinterpret_cast<const float4*>(pp + g * XW + (slot - 1) * 4);
        sm4[s] = v;
    }

    // Kernel taps (overlap with loads before the barrier).
    const int c = plane & (XC - 1);
    const float* kc = kern + c * 9;
    const float k00 = __ldg(kc + 0), k01 = __ldg(kc + 1), k02 = __ldg(kc + 2);
    const float k10 = __ldg(kc + 3), k11 = __ldg(kc + 4), k12 = __ldg(kc + 5);
    const float k20 = __ldg(kc + 6), k21 = __ldg(kc + 7), k22 = __ldg(kc + 8);

    __syncthreads();

    // ---- Compute stage: thread (tx, ty) handles column group t (4 cols) for
    //      7 output rows. All reads are smem; halos already -inf.
    const int tx = tid & 63;
    const int ty = tid >> 6;                   // 0..3
    const bool active = (tx < 56);
    const int t = active ? tx : 55;

    float* op = out + (size_t)plane * (XH * XW) + t * 4;

#pragma unroll
    for (int q = 0; q < 7; q++) {
        const int i = ty * 7 + q;              // local out row; smem rows i..i+2

        const float* rp0 = sm + (i + 0) * SMW + 4 * t;
        const float* rp1 = sm + (i + 1) * SMW + 4 * t;
        const float* rp2 = sm + (i + 2) * SMW + 4 * t;

        float  wl0 = rp0[3], wr0 = rp0[8];
        float4 v0  = *reinterpret_cast<const float4*>(rp0 + 4);
        float  wl1 = rp1[3], wr1 = rp1[8];
        float4 v1  = *reinterpret_cast<const float4*>(rp1 + 4);
        float  wl2 = rp2[3], wr2 = rp2[8];
        float4 v2  = *reinterpret_cast<const float4*>(rp2 + 4);

        // window row 0 assigns, rows 1-2 accumulate
        float a0 = fmaxf(fmaxf(wl0  + k00, v0.x + k01), v0.y + k02);
        float a1 = fmaxf(fmaxf(v0.x + k00, v0.y + k01), v0.z + k02);
        float a2 = fmaxf(fmaxf(v0.y + k00, v0.z + k01), v0.w + k02);
        float a3 = fmaxf(fmaxf(v0.z + k00, v0.w + k01), wr0  + k02);

        a0 = fmaxf(a0, fmaxf(fmaxf(wl1  + k10, v1.x + k11), v1.y + k12));
        a1 = fmaxf(a1, fmaxf(fmaxf(v1.x + k10, v1.y + k11), v1.z + k12));
        a2 = fmaxf(a2, fmaxf(fmaxf(v1.y + k10, v1.z + k11), v1.w + k12));
        a3 = fmaxf(a3, fmaxf(fmaxf(v1.z + k10, v1.w + k11), wr1  + k12));

        a0 = fmaxf(a0, fmaxf(fmaxf(wl2  + k20, v2.x + k21), v2.y + k22));
        a1 = fmaxf(a1, fmaxf(fmaxf(v2.x + k20, v2.y + k21), v2.z + k22));
        a2 = fmaxf(a2, fmaxf(fmaxf(v2.y + k20, v2.z + k21), v2.w + k22));
        a3 = fmaxf(a3, fmaxf(fmaxf(v2.z + k20, v2.w + k21), wr2  + k22));

        if (active) {
            float4 o; o.x = a0; o.y = a1; o.z = a2; o.w = a3;
            __stwt(reinterpret_cast<float4*>(op + (row0 + i) * XW), o);
        }
    }
}

extern "C" void kernel_launch(void* const* d_in, const int* in_sizes, int n_in,
                              void* d_out, int out_size)
{
    const float* x = (const float*)d_in[0];
    const float* k = (const float*)d_in[1];
    float* out = (float*)d_out;

    // Max shared-memory carveout so 8 blocks (217.5 KB) fit per SM.
    cudaFuncSetAttribute(tropical_conv3x3_smem,
                         cudaFuncAttributePreferredSharedMemoryCarveout, 100);

    dim3 block(256, 1, 1);
    dim3 grid(XB * XC * STRIPS, 1, 1);         // 512 * 8 = 4096 blocks
    tropical_conv3x3_smem<<<grid, block>>>(x, k, out);
}

// round 7
// speedup vs baseline: 1.1329x; 1.1329x over previous
#include <cuda_runtime.h>
#include <math_constants.h>

// TropicalConv2D (max-plus 3x3 depthwise), x:(8,64,224,224) f32, k:(64,1,3,3), s=1,p=1,d=1.
// R7: R3 pipeline (best so far) + launch_bounds(256,6) reg cap for 6 blocks/SM,
//     acc_first (no -inf init), hoisted edge select, streaming stores.

#define XB 8
#define XC 64
#define XH 224
#define XW 224
#define W4 56          // float4 groups per row
#define RPT 8          // output rows per thread
#define BY 4           // row strips per block
#define ROWS_PER_BLOCK (RPT * BY)               // 32
#define BLOCKS_PER_PLANE (XH / ROWS_PER_BLOCK)  // 7

#define NEG_INF (-CUDART_INF_F)

struct Raw { float v0, v1, v2, v3, l, r; };
struct Win { float wl, v0, v1, v2, v3, wr; };

__device__ __forceinline__ Raw neg_raw() {
    Raw w; w.v0 = w.v1 = w.v2 = w.v3 = w.l = w.r = NEG_INF; return w;
}

// Load stage: LDG.128 + predicated seam scalars. No shuffles here.
__device__ __forceinline__ Raw load_raw(const float* __restrict__ pp, int r,
                                        int x_eff, int lane) {
    Raw w;
    if (r < 0 || r >= XH) return neg_raw();
    const float* rp = pp + r * XW + x_eff * 4;
    float4 v = *reinterpret_cast<const float4*>(rp);
    w.v0 = v.x; w.v1 = v.y; w.v2 = v.z; w.v3 = v.w;
    w.l = NEG_INF; w.r = NEG_INF;
    if (lane == 0  && x_eff > 0)      w.l = __ldg(rp - 1);
    if (lane == 31 && x_eff < W4 - 1) w.r = __ldg(rp + 4);
    return w;
}

// Window stage: pure SHFL + select. right_edge is loop-invariant (hoisted by caller).
__device__ __forceinline__ Win make_win(const Raw& w, int lane, bool right_edge) {
    Win o;
    o.v0 = w.v0; o.v1 = w.v1; o.v2 = w.v2; o.v3 = w.v3;
    float wl = __shfl_up_sync(0xffffffffu,   w.v3, 1);
    float wr = __shfl_down_sync(0xffffffffu, w.v0, 1);
    o.wl = (lane == 0)  ? w.l : wl;
    o.wr = (lane == 31) ? w.r : wr;
    if (right_edge) o.wr = NEG_INF;
    return o;
}

// First window row assigns accumulators directly (no -inf init, no extra max).
__device__ __forceinline__ void acc_first(const Win& w, float k0, float k1, float k2,
                                          float& a0, float& a1, float& a2, float& a3) {
    a0 = fmaxf(fmaxf(w.wl + k0, w.v0 + k1), w.v1 + k2);
    a1 = fmaxf(fmaxf(w.v0 + k0, w.v1 + k1), w.v2 + k2);
    a2 = fmaxf(fmaxf(w.v1 + k0, w.v2 + k1), w.v3 + k2);
    a3 = fmaxf(fmaxf(w.v2 + k0, w.v3 + k1), w.wr + k2);
}

__device__ __forceinline__ void acc_row(const Win& w, float k0, float k1, float k2,
                                        float& a0, float& a1, float& a2, float& a3) {
    a0 = fmaxf(a0, fmaxf(fmaxf(w.wl + k0, w.v0 + k1), w.v1 + k2));
    a1 = fmaxf(a1, fmaxf(fmaxf(w.v0 + k0, w.v1 + k1), w.v2 + k2));
    a2 = fmaxf(a2, fmaxf(fmaxf(w.v1 + k0, w.v2 + k1), w.v3 + k2));
    a3 = fmaxf(a3, fmaxf(fmaxf(w.v2 + k0, w.v3 + k1), w.wr + k2));
}

__global__ __launch_bounds__(256, 6) void tropical_conv3x3_r7(
    const float* __restrict__ x,
    const float* __restrict__ kern,
    float* __restrict__ out)
{
    const int plane = blockIdx.x / BLOCKS_PER_PLANE;       // b*C + c
    const int strip = blockIdx.x % BLOCKS_PER_PLANE;
    const int tx    = threadIdx.x;                          // 0..63
    const int lane  = tx & 31;
    const int x_eff = (tx < W4) ? tx : (W4 - 1);
    const bool active = (tx < W4);
    const bool right_edge = (x_eff >= W4 - 1);              // loop-invariant
    const int row0  = strip * ROWS_PER_BLOCK + threadIdx.y * RPT;

    const int c = plane & (XC - 1);
    const float* kc = kern + c * 9;
    const float k00 = __ldg(kc + 0), k01 = __ldg(kc + 1), k02 = __ldg(kc + 2);
    const float k10 = __ldg(kc + 3), k11 = __ldg(kc + 4), k12 = __ldg(kc + 5);
    const float k20 = __ldg(kc + 6), k21 = __ldg(kc + 7), k22 = __ldg(kc + 8);

    const float* pp = x   + (size_t)plane * (XH * XW);
    float*       op = out + (size_t)plane * (XH * XW);

    // Prologue: three independent loads in flight, then resolve first two windows.
    Raw rm = load_raw(pp, row0 - 1, x_eff, lane);
    Raw rc = load_raw(pp, row0,     x_eff, lane);
    Raw rp = load_raw(pp, row0 + 1, x_eff, lane);
    Win wm = make_win(rm, lane, right_edge);
    Win wc = make_win(rc, lane, right_edge);

#pragma unroll
    for (int i = 0; i < RPT; i++) {
        const int r = row0 + i;
        // Prefetch row r+2 first; latency covered by this iteration's compute+store.
        Raw rn = load_raw(pp, r + 2, x_eff, lane);
        // Resolve window for row r+1 (raw loaded last iteration).
        Win wp = make_win(rp, lane, right_edge);

        float a0, a1, a2, a3;
        acc_first(wm, k00, k01, k02, a0, a1, a2, a3);
        acc_row  (wc, k10, k11, k12, a0, a1, a2, a3);
        acc_row  (wp, k20, k21, k22, a0, a1, a2, a3);

        if (active) {
            float4 o; o.x = a0; o.y = a1; o.z = a2; o.w = a3;
            __stwt(reinterpret_cast<float4*>(op + r * XW + x_eff * 4), o);
        }
        wm = wc; wc = wp; rp = rn;
    }
}

extern "C" void kernel_launch(void* const* d_in, const int* in_sizes, int n_in,
                              void* d_out, int out_size)
{
    const float* x = (const float*)d_in[0];
    const float* k = (const float*)d_in[1];
    float* out = (float*)d_out;

    dim3 block(64, BY, 1);                                  // 256 threads
    dim3 grid(XB * XC * BLOCKS_PER_PLANE, 1, 1);            // 512 * 7 = 3584 blocks
    tropical_conv3x3_r7<<<grid, block>>>(x, k, out);
}

// round 8
// speedup vs baseline: 1.4464x; 1.2768x over previous
#include <cuda_runtime.h>
#include <math_constants.h>

// TropicalConv2D (max-plus 3x3 depthwise), x:(8,64,224,224) f32, k:(64,1,3,3), s=1,p=1,d=1.
// R8: R3 register pipeline + interior/boundary template specialization (12 of 14 strips
//     run branch-free loads) + finer 128-thread blocks (7168 blocks, ~2% drain tail).

#define XB 8
#define XC 64
#define XH 224
#define XW 224
#define W4 56          // float4 groups per row
#define RPT 8          // output rows per thread
#define BY 2           // row strips per block
#define ROWS_PER_BLOCK (RPT * BY)               // 16
#define STRIPS (XH / ROWS_PER_BLOCK)            // 14

#define NEG_INF (-CUDART_INF_F)

struct Raw { float v0, v1, v2, v3, l, r; };
struct Win { float wl, v0, v1, v2, v3, wr; };

__device__ __forceinline__ Raw neg_raw() {
    Raw w; w.v0 = w.v1 = w.v2 = w.v3 = w.l = w.r = NEG_INF; return w;
}

// Load stage. CHECK=false (interior strips): no row-range test, no neg_raw path.
template<bool CHECK>
__device__ __forceinline__ Raw load_raw(const float* __restrict__ pp, int r,
                                        int x_eff, bool has_l, bool has_r) {
    if (CHECK) { if (r < 0 || r >= XH) return neg_raw(); }
    const float* rp = pp + r * XW + x_eff * 4;
    float4 v = *reinterpret_cast<const float4*>(rp);
    Raw w;
    w.v0 = v.x; w.v1 = v.y; w.v2 = v.z; w.v3 = v.w;
    w.l = has_l ? __ldg(rp - 1) : NEG_INF;
    w.r = has_r ? __ldg(rp + 4) : NEG_INF;
    return w;
}

// Window stage: 2 SHFL + 2 SEL (+1 loop-invariant edge SEL).
__device__ __forceinline__ Win make_win(const Raw& w, int lane, bool right_edge) {
    Win o;
    o.v0 = w.v0; o.v1 = w.v1; o.v2 = w.v2; o.v3 = w.v3;
    float wl = __shfl_up_sync(0xffffffffu,   w.v3, 1);
    float wr = __shfl_down_sync(0xffffffffu, w.v0, 1);
    o.wl = (lane == 0)  ? w.l : wl;
    o.wr = (lane == 31) ? w.r : wr;
    if (right_edge) o.wr = NEG_INF;
    return o;
}

// First window row assigns (no -inf init).
__device__ __forceinline__ void acc_first(const Win& w, float k0, float k1, float k2,
                                          float& a0, float& a1, float& a2, float& a3) {
    a0 = fmaxf(fmaxf(w.wl + k0, w.v0 + k1), w.v1 + k2);
    a1 = fmaxf(fmaxf(w.v0 + k0, w.v1 + k1), w.v2 + k2);
    a2 = fmaxf(fmaxf(w.v1 + k0, w.v2 + k1), w.v3 + k2);
    a3 = fmaxf(fmaxf(w.v2 + k0, w.v3 + k1), w.wr + k2);
}

__device__ __forceinline__ void acc_row(const Win& w, float k0, float k1, float k2,
                                        float& a0, float& a1, float& a2, float& a3) {
    a0 = fmaxf(a0, fmaxf(fmaxf(w.wl + k0, w.v0 + k1), w.v1 + k2));
    a1 = fmaxf(a1, fmaxf(fmaxf(w.v0 + k0, w.v1 + k1), w.v2 + k2));
    a2 = fmaxf(a2, fmaxf(fmaxf(w.v1 + k0, w.v2 + k1), w.v3 + k2));
    a3 = fmaxf(a3, fmaxf(fmaxf(w.v2 + k0, w.v3 + k1), w.wr + k2));
}

template<bool CHECK>
__device__ __forceinline__ void run_strip(
    const float* __restrict__ pp, float* __restrict__ op,
    int row0, int x_eff, int lane, bool active, bool right_edge,
    bool has_l, bool has_r,
    float k00, float k01, float k02,
    float k10, float k11, float k12,
    float k20, float k21, float k22)
{
    // Prologue: three independent loads in flight, then resolve first two windows.
    Raw rm = load_raw<CHECK>(pp, row0 - 1, x_eff, has_l, has_r);
    Raw rc = load_raw<CHECK>(pp, row0,     x_eff, has_l, has_r);
    Raw rp = load_raw<CHECK>(pp, row0 + 1, x_eff, has_l, has_r);
    Win wm = make_win(rm, lane, right_edge);
    Win wc = make_win(rc, lane, right_edge);

#pragma unroll
    for (int i = 0; i < RPT; i++) {
        const int r = row0 + i;
        // Prefetch row r+2 first; latency covered by this iteration's compute+store.
        Raw rn = load_raw<CHECK>(pp, r + 2, x_eff, has_l, has_r);
        // Resolve window for row r+1 (raw loaded last iteration).
        Win wp = make_win(rp, lane, right_edge);

        float a0, a1, a2, a3;
        acc_first(wm, k00, k01, k02, a0, a1, a2, a3);
        acc_row  (wc, k10, k11, k12, a0, a1, a2, a3);
        acc_row  (wp, k20, k21, k22, a0, a1, a2, a3);

        if (active) {
            float4 o; o.x = a0; o.y = a1; o.z = a2; o.w = a3;
            __stwt(reinterpret_cast<float4*>(op + r * XW + x_eff * 4), o);
        }
        wm = wc; wc = wp; rp = rn;
    }
}

__global__ __launch_bounds__(128) void tropical_conv3x3_r8(
    const float* __restrict__ x,
    const float* __restrict__ kern,
    float* __restrict__ out)
{
    const int plane = blockIdx.x / STRIPS;             // b*C + c
    const int strip = blockIdx.x % STRIPS;
    const int tx    = threadIdx.x;                      // 0..63
    const int lane  = tx & 31;
    const int x_eff = (tx < W4) ? tx : (W4 - 1);
    const bool active     = (tx < W4);
    const bool right_edge = (x_eff >= W4 - 1);
    const bool has_l = (lane == 0)  && (x_eff > 0);
    const bool has_r = (lane == 31) && (x_eff < W4 - 1);
    const int row0  = strip * ROWS_PER_BLOCK + threadIdx.y * RPT;

    const int c = plane & (XC - 1);
    const float* kc = kern + c * 9;
    const float k00 = __ldg(kc + 0), k01 = __ldg(kc + 1), k02 = __ldg(kc + 2);
    const float k10 = __ldg(kc + 3), k11 = __ldg(kc + 4), k12 = __ldg(kc + 5);
    const float k20 = __ldg(kc + 6), k21 = __ldg(kc + 7), k22 = __ldg(kc + 8);

    const float* pp = x   + (size_t)plane * (XH * XW);
    float*       op = out + (size_t)plane * (XH * XW);

    if (strip == 0 || strip == STRIPS - 1) {
        run_strip<true >(pp, op, row0, x_eff, lane, active, right_edge, has_l, has_r,
                         k00, k01, k02, k10, k11, k12, k20, k21, k22);
    } else {
        run_strip<false>(pp, op, row0, x_eff, lane, active, right_edge, has_l, has_r,
                         k00, k01, k02, k10, k11, k12, k20, k21, k22);
    }
}

extern "C" void kernel_launch(void* const* d_in, const int* in_sizes, int n_in,
                              void* d_out, int out_size)
{
    const float* x = (const float*)d_in[0];
    const float* k = (const float*)d_in[1];
    float* out = (float*)d_out;

    dim3 block(64, BY, 1);                               // 128 threads
    dim3 grid(XB * XC * STRIPS, 1, 1);                   // 512 * 14 = 7168 blocks
    tropical_conv3x3_r8<<<grid, block>>>(x, k, out);
}

// round 9
// speedup vs baseline: 1.4477x; 1.0009x over previous
#include <cuda_runtime.h>
#include <math_constants.h>

// TropicalConv2D (max-plus 3x3 depthwise), x:(8,64,224,224) f32, k:(64,1,3,3), s=1,p=1,d=1.
// R9: R8 structure + 3-input max.f32 (FMNMX3, sm_90+): 17 -> 13 FP ops per output.

#define XB 8
#define XC 64
#define XH 224
#define XW 224
#define W4 56          // float4 groups per row
#define RPT 8          // output rows per thread
#define BY 2           // row strips per block
#define ROWS_PER_BLOCK (RPT * BY)               // 16
#define STRIPS (XH / ROWS_PER_BLOCK)            // 14

#define NEG_INF (-CUDART_INF_F)

__device__ __forceinline__ float fmax3(float a, float b, float c) {
    float d;
    asm("max.f32 %0, %1, %2, %3;" : "=f"(d) : "f"(a), "f"(b), "f"(c));
    return d;
}

struct Raw { float v0, v1, v2, v3, l, r; };
struct Win { float w[6]; };   // wl, v0..v3, wr

__device__ __forceinline__ Raw neg_raw() {
    Raw w; w.v0 = w.v1 = w.v2 = w.v3 = w.l = w.r = NEG_INF; return w;
}

// Load stage. CHECK=false (interior strips): no row-range test, no neg_raw path.
template<bool CHECK>
__device__ __forceinline__ Raw load_raw(const float* __restrict__ pp, int r,
                                        int x_eff, bool has_l, bool has_r) {
    if (CHECK) { if (r < 0 || r >= XH) return neg_raw(); }
    const float* rp = pp + r * XW + x_eff * 4;
    float4 v = *reinterpret_cast<const float4*>(rp);
    Raw w;
    w.v0 = v.x; w.v1 = v.y; w.v2 = v.z; w.v3 = v.w;
    w.l = has_l ? __ldg(rp - 1) : NEG_INF;
    w.r = has_r ? __ldg(rp + 4) : NEG_INF;
    return w;
}

// Window stage: 2 SHFL + 2 SEL (+1 loop-invariant edge SEL).
__device__ __forceinline__ Win make_win(const Raw& w, int lane, bool right_edge) {
    Win o;
    o.w[1] = w.v0; o.w[2] = w.v1; o.w[3] = w.v2; o.w[4] = w.v3;
    float wl = __shfl_up_sync(0xffffffffu,   w.v3, 1);
    float wr = __shfl_down_sync(0xffffffffu, w.v0, 1);
    o.w[0] = (lane == 0)  ? w.l : wl;
    o.w[5] = (lane == 31) ? w.r : wr;
    if (right_edge) o.w[5] = NEG_INF;
    return o;
}

// Per-window-row horizontal contribution: 3 FADD + 1 FMNMX3 per output.
__device__ __forceinline__ void row_contrib(const Win& w, float k0, float k1, float k2,
                                            float& r0, float& r1, float& r2, float& r3) {
    r0 = fmax3(w.w[0] + k0, w.w[1] + k1, w.w[2] + k2);
    r1 = fmax3(w.w[1] + k0, w.w[2] + k1, w.w[3] + k2);
    r2 = fmax3(w.w[2] + k0, w.w[3] + k1, w.w[4] + k2);
    r3 = fmax3(w.w[3] + k0, w.w[4] + k1, w.w[5] + k2);
}

template<bool CHECK>
__device__ __forceinline__ void run_strip(
    const float* __restrict__ pp, float* __restrict__ op,
    int row0, int x_eff, int lane, bool active, bool right_edge,
    bool has_l, bool has_r,
    float k00, float k01, float k02,
    float k10, float k11, float k12,
    float k20, float k21, float k22)
{
    // Prologue: three independent loads in flight, then resolve first two windows.
    Raw rm = load_raw<CHECK>(pp, row0 - 1, x_eff, has_l, has_r);
    Raw rc = load_raw<CHECK>(pp, row0,     x_eff, has_l, has_r);
    Raw rp = load_raw<CHECK>(pp, row0 + 1, x_eff, has_l, has_r);
    Win wm = make_win(rm, lane, right_edge);
    Win wc = make_win(rc, lane, right_edge);

#pragma unroll
    for (int i = 0; i < RPT; i++) {
        const int r = row0 + i;
        // Prefetch row r+2 first; latency covered by this iteration's compute+store.
        Raw rn = load_raw<CHECK>(pp, r + 2, x_eff, has_l, has_r);
        // Resolve window for row r+1 (raw loaded last iteration).
        Win wp = make_win(rp, lane, right_edge);

        float t0, t1, t2, t3;    // top row contribution
        float m0, m1, m2, m3;    // middle
        float b0, b1, b2, b3;    // bottom
        row_contrib(wm, k00, k01, k02, t0, t1, t2, t3);
        row_contrib(wc, k10, k11, k12, m0, m1, m2, m3);
        row_contrib(wp, k20, k21, k22, b0, b1, b2, b3);

        if (active) {
            float4 o;
            o.x = fmax3(t0, m0, b0);
            o.y = fmax3(t1, m1, b1);
            o.z = fmax3(t2, m2, b2);
            o.w = fmax3(t3, m3, b3);
            __stwt(reinterpret_cast<float4*>(op + r * XW + x_eff * 4), o);
        }
        wm = wc; wc = wp; rp = rn;
    }
}

__global__ __launch_bounds__(128) void tropical_conv3x3_r9(
    const float* __restrict__ x,
    const float* __restrict__ kern,
    float* __restrict__ out)
{
    const int plane = blockIdx.x / STRIPS;             // b*C + c
    const int strip = blockIdx.x % STRIPS;
    const int tx    = threadIdx.x;                      // 0..63
    const int lane  = tx & 31;
    const int x_eff = (tx < W4) ? tx : (W4 - 1);
    const bool active     = (tx < W4);
    const bool right_edge = (x_eff >= W4 - 1);
    const bool has_l = (lane == 0)  && (x_eff > 0);
    const bool has_r = (lane == 31) && (x_eff < W4 - 1);
    const int row0  = strip * ROWS_PER_BLOCK + threadIdx.y * RPT;

    const int c = plane & (XC - 1);
    const float* kc = kern + c * 9;
    const float k00 = __ldg(kc + 0), k01 = __ldg(kc + 1), k02 = __ldg(kc + 2);
    const float k10 = __ldg(kc + 3), k11 = __ldg(kc + 4), k12 = __ldg(kc + 5);
    const float k20 = __ldg(kc + 6), k21 = __ldg(kc + 7), k22 = __ldg(kc + 8);

    const float* pp = x   + (size_t)plane * (XH * XW);
    float*       op = out + (size_t)plane * (XH * XW);

    if (strip == 0 || strip == STRIPS - 1) {
        run_strip<true >(pp, op, row0, x_eff, lane, active, right_edge, has_l, has_r,
                         k00, k01, k02, k10, k11, k12, k20, k21, k22);
    } else {
        run_strip<false>(pp, op, row0, x_eff, lane, active, right_edge, has_l, has_r,
                         k00, k01, k02, k10, k11, k12, k20, k21, k22);
    }
}

extern "C" void kernel_launch(void* const* d_in, const int* in_sizes, int n_in,
                              void* d_out, int out_size)
{
    const float* x = (const float*)d_in[0];
    const float* k = (const float*)d_in[1];
    float* out = (float*)d_out;

    dim3 block(64, BY, 1);                               // 128 threads
    dim3 grid(XB * XC * STRIPS, 1, 1);                   // 512 * 14 = 7168 blocks
    tropical_conv3x3_r9<<<grid, block>>>(x, k, out);
}